// round 1
// baseline (speedup 1.0000x reference)
#include <cuda_runtime.h>
#include <math.h>

// ---------------- scratch (device globals; no allocation allowed) ----------------
__device__ unsigned g_act1[64 * 63 * 63];          // layer1 output, 32ch packed -> 1 word
__device__ unsigned g_act2[64 * 31 * 31 * 2];      // layer2 output, 64ch -> 2 words
__device__ unsigned g_act3[64 * 15 * 15 * 4];      // layer3 output, 128ch -> 4 words
__device__ unsigned g_w2b[64 * 9];                 // [co][tap]
__device__ unsigned g_w3b[128 * 9 * 2];            // [co][tap][wd]
__device__ unsigned g_w4b[256 * 9 * 4];            // [co][tap][wd]

#define BN_EPS 1e-3f

// ---------------- weight sign packing ----------------
// w layout HWIO: w[((kh*3+kw)*Cin + ci)*Cout + co]; bit=1 <=> w>=0 <=> +1
__global__ void k_pack(const float* __restrict__ w2,
                       const float* __restrict__ w3,
                       const float* __restrict__ w4) {
    int i = blockIdx.x * 256 + threadIdx.x;
    if (i < 576) {                       // layer2: 64co x 9tap x 1wd
        int co = i / 9, t = i % 9;
        unsigned bits = 0;
        #pragma unroll
        for (int ci = 0; ci < 32; ci++)
            bits |= ((unsigned)(w2[(t * 32 + ci) * 64 + co] >= 0.f)) << ci;
        g_w2b[co * 9 + t] = bits;
    } else if (i < 576 + 2304) {         // layer3: 128co x 9tap x 2wd
        int j = i - 576;
        int co = j / 18, r = j % 18, t = r / 2, wd = r % 2;
        unsigned bits = 0;
        #pragma unroll
        for (int k = 0; k < 32; k++) {
            int ci = wd * 32 + k;
            bits |= ((unsigned)(w3[(t * 64 + ci) * 128 + co] >= 0.f)) << k;
        }
        g_w3b[(co * 9 + t) * 2 + wd] = bits;
    } else if (i < 576 + 2304 + 9216) {  // layer4: 256co x 9tap x 4wd
        int j = i - 2880;
        int co = j / 36, r = j % 36, t = r / 4, wd = r % 4;
        unsigned bits = 0;
        #pragma unroll
        for (int k = 0; k < 32; k++) {
            int ci = wd * 32 + k;
            bits |= ((unsigned)(w4[(t * 128 + ci) * 256 + co] >= 0.f)) << k;
        }
        g_w4b[(co * 9 + t) * 4 + wd] = bits;
    }
}

// ---------------- layer 1: fp32 conv(VALID) + maxpool + BN-sign -> packed bits ----
// thread = one (b, ph, pw): computes 4 conv positions x 32 channels, packs 1 word
__global__ __launch_bounds__(256) void k_layer1(
        const float* __restrict__ x, const float* __restrict__ w1,
        const float* __restrict__ m1, const float* __restrict__ v1,
        const float* __restrict__ b1) {
    __shared__ float sw[864];   // sign(w1): [tap(27)][co(32)]
    __shared__ float thr[32];
    int tid = threadIdx.x;
    for (int i = tid; i < 864; i += 256) sw[i] = (w1[i] >= 0.f) ? 1.f : -1.f;
    if (tid < 32) thr[tid] = m1[tid] - b1[tid] * sqrtf(v1[tid] + BN_EPS);
    __syncthreads();

    int idx = blockIdx.x * 256 + tid;
    if (idx >= 64 * 63 * 63) return;
    int b = idx / 3969;
    int r = idx % 3969;
    int ph = r / 63, pw = r % 63;

    // 4x4x3 input patch (covers the 2x2 pool window of 3x3 conv taps)
    float px[4][4][3];
    const float* xb = x + (size_t)b * 128 * 128 * 3;
    #pragma unroll
    for (int i = 0; i < 4; i++) {
        const float* row = xb + ((2 * ph + i) * 128 + 2 * pw) * 3;
        #pragma unroll
        for (int j = 0; j < 4; j++)
            #pragma unroll
            for (int c = 0; c < 3; c++)
                px[i][j][c] = __ldg(row + j * 3 + c);
    }

    unsigned word = 0;
    #pragma unroll 2
    for (int co = 0; co < 32; co++) {
        float a0 = 0.f, a1 = 0.f, a2 = 0.f, a3 = 0.f;
        #pragma unroll
        for (int kh = 0; kh < 3; kh++)
            #pragma unroll
            for (int kw = 0; kw < 3; kw++)
                #pragma unroll
                for (int c = 0; c < 3; c++) {
                    float w = sw[((kh * 3 + kw) * 3 + c) * 32 + co];
                    a0 = fmaf(w, px[kh][kw][c], a0);
                    a1 = fmaf(w, px[kh][kw + 1][c], a1);
                    a2 = fmaf(w, px[kh + 1][kw][c], a2);
                    a3 = fmaf(w, px[kh + 1][kw + 1][c], a3);
                }
        float mx = fmaxf(fmaxf(a0, a1), fmaxf(a2, a3));
        word |= ((unsigned)(mx >= thr[co])) << co;
    }
    g_act1[idx] = word;
}

// ---------------- layer 2: binary conv(SAME,63x63,32->64) + pool-threshold ------
// warp = (b, ph, pw, cow); lane = co within word
__global__ __launch_bounds__(256) void k_layer2(
        const float* __restrict__ m2, const float* __restrict__ v2,
        const float* __restrict__ b2) {
    int gt = blockIdx.x * blockDim.x + threadIdx.x;
    int gw = gt >> 5, lane = gt & 31;
    if (gw >= 64 * 31 * 31 * 2) return;
    int cow = gw & 1;
    int p = gw >> 1;
    int b = p / 961;
    int r = p % 961;
    int ph = r / 31, pw = r % 31;
    int co = cow * 32 + lane;

    unsigned w[9];
    #pragma unroll
    for (int t = 0; t < 9; t++) w[t] = g_w2b[co * 9 + t];

    int vr[4], vc[4];
    #pragma unroll
    for (int i = 0; i < 4; i++) {
        vr[i] = ((unsigned)(2 * ph - 1 + i) < 63u);
        vc[i] = ((unsigned)(2 * pw - 1 + i) < 63u);
    }
    unsigned a[4][4];
    const unsigned* ab = g_act1 + b * 3969;
    #pragma unroll
    for (int i = 0; i < 4; i++)
        #pragma unroll
        for (int j = 0; j < 4; j++)
            a[i][j] = (vr[i] && vc[j]) ? ab[(2 * ph - 1 + i) * 63 + (2 * pw - 1 + j)] : 0u;

    int best;
    if (vr[0] & vr[3] & vc[0] & vc[3]) {   // interior fast path
        int pmin = 1 << 30;
        #pragma unroll
        for (int dy = 0; dy < 2; dy++)
            #pragma unroll
            for (int dx = 0; dx < 2; dx++) {
                int P = 0;
                #pragma unroll
                for (int kh = 0; kh < 3; kh++)
                    #pragma unroll
                    for (int kw = 0; kw < 3; kw++)
                        P += __popc(a[dy + kh][dx + kw] ^ w[kh * 3 + kw]);
                pmin = (P < pmin) ? P : pmin;
            }
        best = 288 - 2 * pmin;
    } else {
        best = -100000;
        #pragma unroll
        for (int dy = 0; dy < 2; dy++)
            #pragma unroll
            for (int dx = 0; dx < 2; dx++) {
                int dot = 0;
                #pragma unroll
                for (int kh = 0; kh < 3; kh++)
                    #pragma unroll
                    for (int kw = 0; kw < 3; kw++) {
                        int s = __popc(a[dy + kh][dx + kw] ^ w[kh * 3 + kw]);
                        dot += (vr[dy + kh] & vc[dx + kw]) ? (32 - 2 * s) : 0;
                    }
                best = (dot > best) ? dot : best;
            }
    }
    float thr = m2[co] - b2[co] * sqrtf(v2[co] + BN_EPS);
    unsigned word = __ballot_sync(0xffffffffu, (float)best >= thr);
    if (lane == 0) g_act2[p * 2 + cow] = word;
}

// ---------------- layer 3: binary conv(SAME,31x31,64->128) + pool-threshold -----
__global__ __launch_bounds__(256) void k_layer3(
        const float* __restrict__ m3, const float* __restrict__ v3,
        const float* __restrict__ b3) {
    int gt = blockIdx.x * blockDim.x + threadIdx.x;
    int gw = gt >> 5, lane = gt & 31;
    if (gw >= 64 * 15 * 15 * 4) return;
    int cow = gw & 3;
    int p = gw >> 2;
    int b = p / 225;
    int r = p % 225;
    int ph = r / 15, pw = r % 15;
    int co = cow * 32 + lane;

    unsigned w[9][2];
    #pragma unroll
    for (int t = 0; t < 9; t++) {
        w[t][0] = g_w3b[(co * 9 + t) * 2 + 0];
        w[t][1] = g_w3b[(co * 9 + t) * 2 + 1];
    }
    int vr[4], vc[4];
    #pragma unroll
    for (int i = 0; i < 4; i++) {
        vr[i] = ((unsigned)(2 * ph - 1 + i) < 31u);
        vc[i] = ((unsigned)(2 * pw - 1 + i) < 31u);
    }
    unsigned a[4][4][2];
    const unsigned* ab = g_act2 + b * 31 * 31 * 2;
    #pragma unroll
    for (int i = 0; i < 4; i++)
        #pragma unroll
        for (int j = 0; j < 4; j++) {
            if (vr[i] && vc[j]) {
                const unsigned* q = ab + ((2 * ph - 1 + i) * 31 + (2 * pw - 1 + j)) * 2;
                a[i][j][0] = q[0];
                a[i][j][1] = q[1];
            } else {
                a[i][j][0] = 0u;
                a[i][j][1] = 0u;
            }
        }

    int best;
    if (vr[0] & vr[3] & vc[0] & vc[3]) {
        int pmin = 1 << 30;
        #pragma unroll
        for (int dy = 0; dy < 2; dy++)
            #pragma unroll
            for (int dx = 0; dx < 2; dx++) {
                int P = 0;
                #pragma unroll
                for (int kh = 0; kh < 3; kh++)
                    #pragma unroll
                    for (int kw = 0; kw < 3; kw++) {
                        P += __popc(a[dy + kh][dx + kw][0] ^ w[kh * 3 + kw][0]);
                        P += __popc(a[dy + kh][dx + kw][1] ^ w[kh * 3 + kw][1]);
                    }
                pmin = (P < pmin) ? P : pmin;
            }
        best = 576 - 2 * pmin;
    } else {
        best = -100000;
        #pragma unroll
        for (int dy = 0; dy < 2; dy++)
            #pragma unroll
            for (int dx = 0; dx < 2; dx++) {
                int dot = 0;
                #pragma unroll
                for (int kh = 0; kh < 3; kh++)
                    #pragma unroll
                    for (int kw = 0; kw < 3; kw++) {
                        int s = __popc(a[dy + kh][dx + kw][0] ^ w[kh * 3 + kw][0])
                              + __popc(a[dy + kh][dx + kw][1] ^ w[kh * 3 + kw][1]);
                        dot += (vr[dy + kh] & vc[dx + kw]) ? (64 - 2 * s) : 0;
                    }
                best = (dot > best) ? dot : best;
            }
    }
    float thr = m3[co] - b3[co] * sqrtf(v3[co] + BN_EPS);
    unsigned word = __ballot_sync(0xffffffffu, (float)best >= thr);
    if (lane == 0) g_act3[p * 4 + cow] = word;
}

// ---------------- layer 4: binary conv(SAME,15x15,128->256) + pool + BN (fp32 out)
__global__ __launch_bounds__(256) void k_layer4(
        const float* __restrict__ m4, const float* __restrict__ v4,
        const float* __restrict__ b4, float* __restrict__ out) {
    int gt = blockIdx.x * blockDim.x + threadIdx.x;
    int gw = gt >> 5, lane = gt & 31;
    if (gw >= 64 * 7 * 7 * 8) return;
    int cow = gw & 7;
    int p = gw >> 3;
    int b = p / 49;
    int r = p % 49;
    int ph = r / 7, pw = r % 7;
    int co = cow * 32 + lane;

    unsigned w[9][4];
    #pragma unroll
    for (int t = 0; t < 9; t++)
        #pragma unroll
        for (int wd = 0; wd < 4; wd++)
            w[t][wd] = g_w4b[(co * 9 + t) * 4 + wd];

    int vr[4], vc[4];
    #pragma unroll
    for (int i = 0; i < 4; i++) {
        vr[i] = ((unsigned)(2 * ph - 1 + i) < 15u);
        vc[i] = ((unsigned)(2 * pw - 1 + i) < 15u);
    }
    unsigned a[4][4][4];
    const unsigned* ab = g_act3 + b * 15 * 15 * 4;
    #pragma unroll
    for (int i = 0; i < 4; i++)
        #pragma unroll
        for (int j = 0; j < 4; j++) {
            if (vr[i] && vc[j]) {
                const unsigned* q = ab + ((2 * ph - 1 + i) * 15 + (2 * pw - 1 + j)) * 4;
                #pragma unroll
                for (int wd = 0; wd < 4; wd++) a[i][j][wd] = q[wd];
            } else {
                #pragma unroll
                for (int wd = 0; wd < 4; wd++) a[i][j][wd] = 0u;
            }
        }

    int best;
    if (vr[0] & vr[3] & vc[0] & vc[3]) {
        int pmin = 1 << 30;
        #pragma unroll
        for (int dy = 0; dy < 2; dy++)
            #pragma unroll
            for (int dx = 0; dx < 2; dx++) {
                int P = 0;
                #pragma unroll
                for (int kh = 0; kh < 3; kh++)
                    #pragma unroll
                    for (int kw = 0; kw < 3; kw++)
                        #pragma unroll
                        for (int wd = 0; wd < 4; wd++)
                            P += __popc(a[dy + kh][dx + kw][wd] ^ w[kh * 3 + kw][wd]);
                pmin = (P < pmin) ? P : pmin;
            }
        best = 1152 - 2 * pmin;
    } else {
        best = -100000;
        #pragma unroll
        for (int dy = 0; dy < 2; dy++)
            #pragma unroll
            for (int dx = 0; dx < 2; dx++) {
                int dot = 0;
                #pragma unroll
                for (int kh = 0; kh < 3; kh++)
                    #pragma unroll
                    for (int kw = 0; kw < 3; kw++) {
                        int s = 0;
                        #pragma unroll
                        for (int wd = 0; wd < 4; wd++)
                            s += __popc(a[dy + kh][dx + kw][wd] ^ w[kh * 3 + kw][wd]);
                        dot += (vr[dy + kh] & vc[dx + kw]) ? (128 - 2 * s) : 0;
                    }
                best = (dot > best) ? dot : best;
            }
    }
    float o = ((float)best - m4[co]) * rsqrtf(v4[co] + BN_EPS) + b4[co];
    out[p * 256 + co] = o;
}

// ---------------- launch ----------------
extern "C" void kernel_launch(void* const* d_in, const int* in_sizes, int n_in,
                              void* d_out, int out_size) {
    const float* x  = (const float*)d_in[0];
    const float* w1 = (const float*)d_in[1];
    const float* m1 = (const float*)d_in[2];
    const float* v1 = (const float*)d_in[3];
    const float* b1 = (const float*)d_in[4];
    const float* w2 = (const float*)d_in[5];
    const float* m2 = (const float*)d_in[6];
    const float* v2 = (const float*)d_in[7];
    const float* b2 = (const float*)d_in[8];
    const float* w3 = (const float*)d_in[9];
    const float* m3 = (const float*)d_in[10];
    const float* v3 = (const float*)d_in[11];
    const float* b3 = (const float*)d_in[12];
    const float* w4 = (const float*)d_in[13];
    const float* m4 = (const float*)d_in[14];
    const float* v4 = (const float*)d_in[15];
    const float* b4 = (const float*)d_in[16];
    float* out = (float*)d_out;

    k_pack<<<48, 256>>>(w2, w3, w4);
    k_layer1<<<(64 * 63 * 63 + 255) / 256, 256>>>(x, w1, m1, v1, b1);
    k_layer2<<<(64 * 31 * 31 * 2) / 8, 256>>>(m2, v2, b2);
    k_layer3<<<(64 * 15 * 15 * 4) / 8, 256>>>(m3, v3, b3);
    k_layer4<<<(64 * 7 * 7 * 8) / 8, 256>>>(m4, v4, b4, out);
}

// round 2
// speedup vs baseline: 1.0653x; 1.0653x over previous
#include <cuda_runtime.h>
#include <math.h>

typedef unsigned long long ull;

// ---------------- scratch (device globals; no allocation allowed) ----------------
__device__ unsigned g_act1[64 * 63 * 63];          // layer1 output, 32ch packed
__device__ unsigned g_act2[64 * 31 * 31 * 2];      // layer2 output, 64ch -> 2 words
__device__ unsigned g_act3[64 * 15 * 15 * 4];      // layer3 output, 128ch -> 4 words
__device__ unsigned g_w2b[64 * 9];                 // [co][tap]
__device__ unsigned g_w3b[128 * 9 * 2];            // [co][tap][wd]
__device__ unsigned g_w4b[256 * 9 * 4];            // [co][tap][wd]
__device__ float    g_thr2[64];
__device__ float    g_thr3[128];

#define BN_EPS 1e-3f

// ---------------- f32x2 helpers (Blackwell packed fp32) ----------------
__device__ __forceinline__ ull pack2(float lo, float hi) {
    ull r; asm("mov.b64 %0, {%1, %2};" : "=l"(r) : "f"(lo), "f"(hi)); return r;
}
__device__ __forceinline__ void unpack2(float& lo, float& hi, ull v) {
    asm("mov.b64 {%0, %1}, %2;" : "=f"(lo), "=f"(hi) : "l"(v));
}
__device__ __forceinline__ ull ffma2(ull a, ull b, ull c) {
    ull d; asm("fma.rn.f32x2 %0, %1, %2, %3;" : "=l"(d) : "l"(a), "l"(b), "l"(c)); return d;
}

// ---------------- weight sign packing + BN thresholds ----------------
__global__ void k_pack(const float* __restrict__ w2,
                       const float* __restrict__ w3,
                       const float* __restrict__ w4,
                       const float* __restrict__ m2, const float* __restrict__ v2,
                       const float* __restrict__ b2,
                       const float* __restrict__ m3, const float* __restrict__ v3,
                       const float* __restrict__ b3) {
    int i = blockIdx.x * 256 + threadIdx.x;
    if (i < 576) {                       // layer2: 64co x 9tap
        int co = i / 9, t = i % 9;
        unsigned bits = 0;
        #pragma unroll
        for (int ci = 0; ci < 32; ci++)
            bits |= ((unsigned)(w2[(t * 32 + ci) * 64 + co] >= 0.f)) << ci;
        g_w2b[co * 9 + t] = bits;
    } else if (i < 576 + 2304) {         // layer3: 128co x 9tap x 2wd
        int j = i - 576;
        int co = j / 18, r = j % 18, t = r / 2, wd = r % 2;
        unsigned bits = 0;
        #pragma unroll
        for (int k = 0; k < 32; k++) {
            int ci = wd * 32 + k;
            bits |= ((unsigned)(w3[(t * 64 + ci) * 128 + co] >= 0.f)) << k;
        }
        g_w3b[(co * 9 + t) * 2 + wd] = bits;
    } else if (i < 576 + 2304 + 9216) {  // layer4: 256co x 9tap x 4wd
        int j = i - 2880;
        int co = j / 36, r = j % 36, t = r / 4, wd = r % 4;
        unsigned bits = 0;
        #pragma unroll
        for (int k = 0; k < 32; k++) {
            int ci = wd * 32 + k;
            bits |= ((unsigned)(w4[(t * 128 + ci) * 256 + co] >= 0.f)) << k;
        }
        g_w4b[(co * 9 + t) * 4 + wd] = bits;
    } else if (i < 12096 + 64) {
        int j = i - 12096;
        g_thr2[j] = m2[j] - b2[j] * sqrtf(v2[j] + BN_EPS);
    } else if (i < 12096 + 192) {
        int j = i - 12160;
        g_thr3[j] = m3[j] - b3[j] * sqrtf(v3[j] + BN_EPS);
    }
}

// ---------------- layer 1: fp32 conv(VALID) + maxpool + BN-sign, via FFMA2 ------
// thread = one (b, ph, pw): 4 conv positions x 32 channels, packed 2-wide in f32x2
__global__ __launch_bounds__(256) void k_layer1(
        const float* __restrict__ x, const float* __restrict__ w1,
        const float* __restrict__ m1, const float* __restrict__ v1,
        const float* __restrict__ b1) {
    __shared__ ull sw2[32 * 28];   // [co][k] packed {s,s}, k=(kh*3+kw)*3+c, pad 28
    __shared__ float thr[32];
    int tid = threadIdx.x;
    for (int i = tid; i < 864; i += 256) {
        float s = (w1[i] >= 0.f) ? 1.f : -1.f;
        int k = i >> 5, co = i & 31;
        sw2[co * 28 + k] = pack2(s, s);
    }
    if (tid < 32) thr[tid] = m1[tid] - b1[tid] * sqrtf(v1[tid] + BN_EPS);
    __syncthreads();

    int idx = blockIdx.x * 256 + tid;
    if (idx >= 64 * 63 * 63) return;
    int b = idx / 3969;
    int r = idx % 3969;
    int ph = r / 63, pw = r % 63;

    // load 4x4x3 patch, build x pairs xa[row][kw*3+c] = {x[kw], x[kw+1]} (over cols)
    ull xa[4][9];
    const float* xb = x + (size_t)b * 128 * 128 * 3;
    #pragma unroll
    for (int i = 0; i < 4; i++) {
        const float* row = xb + ((2 * ph + i) * 128 + 2 * pw) * 3;
        float f[12];
        #pragma unroll
        for (int j = 0; j < 6; j++) {
            float2 t2 = __ldg((const float2*)row + j);
            f[2 * j] = t2.x; f[2 * j + 1] = t2.y;
        }
        #pragma unroll
        for (int kw = 0; kw < 3; kw++)
            #pragma unroll
            for (int c = 0; c < 3; c++)
                xa[i][kw * 3 + c] = pack2(f[kw * 3 + c], f[kw * 3 + c + 3]);
    }

    unsigned word = 0;
    #pragma unroll 2
    for (int co = 0; co < 32; co++) {
        const ull* wr = &sw2[co * 28];
        ull acc0 = 0ull, acc1 = 0ull;   // {dx=0,dx=1} for dy=0 and dy=1
        #pragma unroll
        for (int k = 0; k < 27; k++) {
            int kh = k / 9, rem = k % 9;
            ull w = wr[k];
            acc0 = ffma2(w, xa[kh][rem], acc0);
            acc1 = ffma2(w, xa[kh + 1][rem], acc1);
        }
        float a0, a1, a2, a3;
        unpack2(a0, a1, acc0);
        unpack2(a2, a3, acc1);
        float mx = fmaxf(fmaxf(a0, a1), fmaxf(a2, a3));
        word |= ((unsigned)(mx >= thr[co])) << co;
    }
    g_act1[idx] = word;
}

// ---------------- layer 2: binary conv(SAME,63x63,32->64) + pool-threshold ------
__global__ __launch_bounds__(256) void k_layer2() {
    int gt = blockIdx.x * blockDim.x + threadIdx.x;
    int gw = gt >> 5, lane = gt & 31;
    if (gw >= 64 * 31 * 31 * 2) return;
    int cow = gw & 1;
    int p = gw >> 1;
    int b = p / 961;
    int r = p % 961;
    int ph = r / 31, pw = r % 31;
    int co = cow * 32 + lane;

    unsigned w[9];
    #pragma unroll
    for (int t = 0; t < 9; t++) w[t] = g_w2b[co * 9 + t];

    const unsigned* ab = g_act1 + b * 3969;
    int best;
    if (ph > 0 && pw > 0) {            // interior (cells 2ph-1..2ph+2 all valid)
        int P0 = 0, P1 = 0, P2 = 0, P3 = 0;
        #pragma unroll
        for (int i = 0; i < 4; i++) {
            const unsigned* rp = ab + (2 * ph - 1 + i) * 63 + (2 * pw - 1);
            unsigned a0 = rp[0], a1 = rp[1], a2 = rp[2], a3 = rp[3];
            if (i < 3) {
                int kh = i;
                P0 += __popc(a0 ^ w[kh * 3]) + __popc(a1 ^ w[kh * 3 + 1]) + __popc(a2 ^ w[kh * 3 + 2]);
                P1 += __popc(a1 ^ w[kh * 3]) + __popc(a2 ^ w[kh * 3 + 1]) + __popc(a3 ^ w[kh * 3 + 2]);
            }
            if (i >= 1) {
                int kh = i - 1;
                P2 += __popc(a0 ^ w[kh * 3]) + __popc(a1 ^ w[kh * 3 + 1]) + __popc(a2 ^ w[kh * 3 + 2]);
                P3 += __popc(a1 ^ w[kh * 3]) + __popc(a2 ^ w[kh * 3 + 1]) + __popc(a3 ^ w[kh * 3 + 2]);
            }
        }
        int pmin = min(min(P0, P1), min(P2, P3));
        best = 288 - 2 * pmin;
    } else {                            // border
        int D[4] = {0, 0, 0, 0};
        #pragma unroll
        for (int i = 0; i < 4; i++) {
            int rr = 2 * ph - 1 + i;
            bool vri = ((unsigned)rr < 63u);
            unsigned a[4]; bool vc[4];
            #pragma unroll
            for (int j = 0; j < 4; j++) {
                int cc = 2 * pw - 1 + j;
                vc[j] = ((unsigned)cc < 63u);
                a[j] = (vri && vc[j]) ? ab[rr * 63 + cc] : 0u;
            }
            #pragma unroll
            for (int dy = 0; dy < 2; dy++) {
                int kh = i - dy;
                if (kh >= 0 && kh < 3) {
                    #pragma unroll
                    for (int dx = 0; dx < 2; dx++)
                        #pragma unroll
                        for (int kw = 0; kw < 3; kw++) {
                            int j = dx + kw;
                            int s = __popc(a[j] ^ w[kh * 3 + kw]);
                            D[dy * 2 + dx] += (vri && vc[j]) ? (32 - 2 * s) : 0;
                        }
                }
            }
        }
        best = max(max(D[0], D[1]), max(D[2], D[3]));
    }
    float thr = g_thr2[co];
    unsigned word = __ballot_sync(0xffffffffu, (float)best >= thr);
    if (lane == 0) g_act2[p * 2 + cow] = word;
}

// ---------------- layer 3: binary conv(SAME,31x31,64->128) + pool-threshold -----
__device__ __forceinline__ int popc2(uint2 a, uint2 b) {
    return __popc(a.x ^ b.x) + __popc(a.y ^ b.y);
}
__global__ __launch_bounds__(256) void k_layer3() {
    int gt = blockIdx.x * blockDim.x + threadIdx.x;
    int gw = gt >> 5, lane = gt & 31;
    if (gw >= 64 * 15 * 15 * 4) return;
    int cow = gw & 3;
    int p = gw >> 2;
    int b = p / 225;
    int r = p % 225;
    int ph = r / 15, pw = r % 15;
    int co = cow * 32 + lane;

    uint2 w[9];
    #pragma unroll
    for (int t = 0; t < 9; t++) w[t] = ((const uint2*)g_w3b)[co * 9 + t];

    const uint2* ab = (const uint2*)g_act2 + b * 31 * 31;
    int best;
    if (ph > 0 && pw > 0) {
        int P0 = 0, P1 = 0, P2 = 0, P3 = 0;
        #pragma unroll
        for (int i = 0; i < 4; i++) {
            const uint2* rp = ab + (2 * ph - 1 + i) * 31 + (2 * pw - 1);
            uint2 a0 = rp[0], a1 = rp[1], a2 = rp[2], a3 = rp[3];
            if (i < 3) {
                int kh = i;
                P0 += popc2(a0, w[kh * 3]) + popc2(a1, w[kh * 3 + 1]) + popc2(a2, w[kh * 3 + 2]);
                P1 += popc2(a1, w[kh * 3]) + popc2(a2, w[kh * 3 + 1]) + popc2(a3, w[kh * 3 + 2]);
            }
            if (i >= 1) {
                int kh = i - 1;
                P2 += popc2(a0, w[kh * 3]) + popc2(a1, w[kh * 3 + 1]) + popc2(a2, w[kh * 3 + 2]);
                P3 += popc2(a1, w[kh * 3]) + popc2(a2, w[kh * 3 + 1]) + popc2(a3, w[kh * 3 + 2]);
            }
        }
        int pmin = min(min(P0, P1), min(P2, P3));
        best = 576 - 2 * pmin;
    } else {
        int D[4] = {0, 0, 0, 0};
        #pragma unroll
        for (int i = 0; i < 4; i++) {
            int rr = 2 * ph - 1 + i;
            bool vri = ((unsigned)rr < 31u);
            uint2 a[4]; bool vc[4];
            #pragma unroll
            for (int j = 0; j < 4; j++) {
                int cc = 2 * pw - 1 + j;
                vc[j] = ((unsigned)cc < 31u);
                a[j] = (vri && vc[j]) ? ab[rr * 31 + cc] : make_uint2(0u, 0u);
            }
            #pragma unroll
            for (int dy = 0; dy < 2; dy++) {
                int kh = i - dy;
                if (kh >= 0 && kh < 3) {
                    #pragma unroll
                    for (int dx = 0; dx < 2; dx++)
                        #pragma unroll
                        for (int kw = 0; kw < 3; kw++) {
                            int j = dx + kw;
                            int s = popc2(a[j], w[kh * 3 + kw]);
                            D[dy * 2 + dx] += (vri && vc[j]) ? (64 - 2 * s) : 0;
                        }
                }
            }
        }
        best = max(max(D[0], D[1]), max(D[2], D[3]));
    }
    float thr = g_thr3[co];
    unsigned word = __ballot_sync(0xffffffffu, (float)best >= thr);
    if (lane == 0) g_act3[p * 4 + cow] = word;
}

// ---------------- layer 4: binary conv(SAME,15x15,128->256) + pool + BN ----------
__device__ __forceinline__ int popc4(uint4 a, uint4 b) {
    return __popc(a.x ^ b.x) + __popc(a.y ^ b.y) + __popc(a.z ^ b.z) + __popc(a.w ^ b.w);
}
__global__ __launch_bounds__(256) void k_layer4(
        const float* __restrict__ m4, const float* __restrict__ v4,
        const float* __restrict__ b4, float* __restrict__ out) {
    int gt = blockIdx.x * blockDim.x + threadIdx.x;
    int gw = gt >> 5, lane = gt & 31;
    if (gw >= 64 * 7 * 7 * 8) return;
    int cow = gw & 7;
    int p = gw >> 3;
    int b = p / 49;
    int r = p % 49;
    int ph = r / 7, pw = r % 7;
    int co = cow * 32 + lane;

    uint4 w[9];
    #pragma unroll
    for (int t = 0; t < 9; t++) w[t] = ((const uint4*)g_w4b)[co * 9 + t];

    const uint4* ab = (const uint4*)g_act3 + b * 15 * 15;
    int best;
    if (ph > 0 && pw > 0) {
        int P0 = 0, P1 = 0, P2 = 0, P3 = 0;
        #pragma unroll
        for (int i = 0; i < 4; i++) {
            const uint4* rp = ab + (2 * ph - 1 + i) * 15 + (2 * pw - 1);
            uint4 a0 = rp[0], a1 = rp[1], a2 = rp[2], a3 = rp[3];
            if (i < 3) {
                int kh = i;
                P0 += popc4(a0, w[kh * 3]) + popc4(a1, w[kh * 3 + 1]) + popc4(a2, w[kh * 3 + 2]);
                P1 += popc4(a1, w[kh * 3]) + popc4(a2, w[kh * 3 + 1]) + popc4(a3, w[kh * 3 + 2]);
            }
            if (i >= 1) {
                int kh = i - 1;
                P2 += popc4(a0, w[kh * 3]) + popc4(a1, w[kh * 3 + 1]) + popc4(a2, w[kh * 3 + 2]);
                P3 += popc4(a1, w[kh * 3]) + popc4(a2, w[kh * 3 + 1]) + popc4(a3, w[kh * 3 + 2]);
            }
        }
        int pmin = min(min(P0, P1), min(P2, P3));
        best = 1152 - 2 * pmin;
    } else {
        int D[4] = {0, 0, 0, 0};
        #pragma unroll
        for (int i = 0; i < 4; i++) {
            int rr = 2 * ph - 1 + i;
            bool vri = ((unsigned)rr < 15u);
            uint4 a[4]; bool vc[4];
            #pragma unroll
            for (int j = 0; j < 4; j++) {
                int cc = 2 * pw - 1 + j;
                vc[j] = ((unsigned)cc < 15u);
                a[j] = (vri && vc[j]) ? ab[rr * 15 + cc] : make_uint4(0u, 0u, 0u, 0u);
            }
            #pragma unroll
            for (int dy = 0; dy < 2; dy++) {
                int kh = i - dy;
                if (kh >= 0 && kh < 3) {
                    #pragma unroll
                    for (int dx = 0; dx < 2; dx++)
                        #pragma unroll
                        for (int kw = 0; kw < 3; kw++) {
                            int j = dx + kw;
                            int s = popc4(a[j], w[kh * 3 + kw]);
                            D[dy * 2 + dx] += (vri && vc[j]) ? (128 - 2 * s) : 0;
                        }
                }
            }
        }
        best = max(max(D[0], D[1]), max(D[2], D[3]));
    }
    float o = ((float)best - m4[co]) * rsqrtf(v4[co] + BN_EPS) + b4[co];
    out[p * 256 + co] = o;
}

// ---------------- launch ----------------
extern "C" void kernel_launch(void* const* d_in, const int* in_sizes, int n_in,
                              void* d_out, int out_size) {
    const float* x  = (const float*)d_in[0];
    const float* w1 = (const float*)d_in[1];
    const float* m1 = (const float*)d_in[2];
    const float* v1 = (const float*)d_in[3];
    const float* b1 = (const float*)d_in[4];
    const float* w2 = (const float*)d_in[5];
    const float* m2 = (const float*)d_in[6];
    const float* v2 = (const float*)d_in[7];
    const float* b2 = (const float*)d_in[8];
    const float* w3 = (const float*)d_in[9];
    const float* m3 = (const float*)d_in[10];
    const float* v3 = (const float*)d_in[11];
    const float* b3 = (const float*)d_in[12];
    const float* w4 = (const float*)d_in[13];
    const float* m4 = (const float*)d_in[14];
    const float* v4 = (const float*)d_in[15];
    const float* b4 = (const float*)d_in[16];
    float* out = (float*)d_out;

    k_pack<<<48, 256>>>(w2, w3, w4, m2, v2, b2, m3, v3, b3);
    k_layer1<<<(64 * 63 * 63 + 255) / 256, 256>>>(x, w1, m1, v1, b1);
    k_layer2<<<(64 * 31 * 31 * 2 * 32) / 256, 256>>>();
    k_layer3<<<(64 * 15 * 15 * 4 * 32) / 256, 256>>>();
    k_layer4<<<(64 * 7 * 7 * 8 * 32) / 256, 256>>>(m4, v4, b4, out);
}